// round 12
// baseline (speedup 1.0000x reference)
#include <cuda_runtime.h>
#include <cuda_fp16.h>
#include <cstdint>
#include <math.h>

// Problem dims (fixed by the dataset)
#define Bc 256
#define Nc 4096
#define Mc 16384
#define STEPS 50

// ---------------------------------------------------------------------------
// Device-global scratch
// ---------------------------------------------------------------------------
__device__ __half g_Wh[(size_t)Mc * Nc];    // W fp16 [m][n] (both GEMMs)
__device__ __half g_sh[(size_t)Bc * Nc];    // state fp16 [b][n]
__device__ __half g_fh[(size_t)Bc * Mc];    // e = exp(beta*h) fp16 [b][m]
__device__ float  g_fsum [Bc];              // row sums (accumulating)
__device__ float  g_fsum2[Bc];              // snapshot read by update
__device__ float  g_vpart[4][(size_t)Bc * Nc];
__device__ float  g_norm[STEPS];

__device__ unsigned g_cnt_bar;
__device__ volatile unsigned g_gen_bar;

// ---------------------------------------------------------------------------
// PTX helpers (sm_80-era, legal on plain sm_103)
// ---------------------------------------------------------------------------
__device__ __forceinline__ uint32_t s2u(const void* p) {
    return (uint32_t)__cvta_generic_to_shared(p);
}
__device__ __forceinline__ void cpa16(uint32_t dst, const void* src) {
    asm volatile("cp.async.cg.shared.global [%0], [%1], 16;" :: "r"(dst), "l"(src));
}
#define CP_COMMIT() asm volatile("cp.async.commit_group;" ::: "memory")
#define CP_WAIT(n)  asm volatile("cp.async.wait_group %0;" :: "n"(n) : "memory")

__device__ __forceinline__ void ldm4(uint32_t* r, uint32_t addr) {
    asm volatile("ldmatrix.sync.aligned.m8n8.x4.shared.b16 {%0,%1,%2,%3}, [%4];"
                 : "=r"(r[0]), "=r"(r[1]), "=r"(r[2]), "=r"(r[3]) : "r"(addr));
}
__device__ __forceinline__ void ldm4t(uint32_t* r, uint32_t addr) {
    asm volatile("ldmatrix.sync.aligned.m8n8.x4.trans.shared.b16 {%0,%1,%2,%3}, [%4];"
                 : "=r"(r[0]), "=r"(r[1]), "=r"(r[2]), "=r"(r[3]) : "r"(addr));
}
__device__ __forceinline__ void mma16816(float* d, const uint32_t* a,
                                         uint32_t b0, uint32_t b1) {
    asm volatile(
        "mma.sync.aligned.m16n8k16.row.col.f32.f16.f16.f32 "
        "{%0,%1,%2,%3}, {%4,%5,%6,%7}, {%8,%9}, {%0,%1,%2,%3};"
        : "+f"(d[0]), "+f"(d[1]), "+f"(d[2]), "+f"(d[3])
        : "r"(a[0]), "r"(a[1]), "r"(a[2]), "r"(a[3]), "r"(b0), "r"(b1));
}

// ---------------------------------------------------------------------------
// Software global barrier (all launched CTAs co-resident)
// ---------------------------------------------------------------------------
__device__ __forceinline__ void gbar(int G) {
    __syncthreads();
    if (threadIdx.x == 0) {
        __threadfence();
        unsigned my = g_gen_bar;
        unsigned old = atomicAdd(&g_cnt_bar, 1u);
        if (old == (unsigned)G - 1u) {
            g_cnt_bar = 0u;
            __threadfence();
            g_gen_bar = my + 1u;
        } else {
            while (g_gen_bar == my) __nanosleep(64);
        }
        __threadfence();
    }
    __syncthreads();
}

// ---------------------------------------------------------------------------
// Prologue: W -> fp16, state <- input (+fp16), zero norms/sums (one kernel)
// ---------------------------------------------------------------------------
__global__ void __launch_bounds__(256) k_prep(const float* __restrict__ W,
                                              const float* __restrict__ inp,
                                              float* __restrict__ state) {
    size_t i = (size_t)blockIdx.x * 1024 + threadIdx.x * 4;
    float4 v = *(const float4*)(W + i);
    *(__half2*)(g_Wh + i)     = __floats2half2_rn(v.x, v.y);
    *(__half2*)(g_Wh + i + 2) = __floats2half2_rn(v.z, v.w);

    if (blockIdx.x < (Bc * Nc) / 1024) {
        float4 s = *(const float4*)(inp + i);
        *(float4*)(state + i) = s;
        *(__half2*)(g_sh + i)     = __floats2half2_rn(s.x, s.y);
        *(__half2*)(g_sh + i + 2) = __floats2half2_rn(s.z, s.w);
    }
    int gid = blockIdx.x * 256 + threadIdx.x;
    if (gid < STEPS) g_norm[gid] = 0.0f;
    if (gid < Bc) { g_fsum[gid] = 0.0f; g_fsum2[gid] = 0.0f; }
}

// ---------------------------------------------------------------------------
// Shared sizes.  CTA = 256 threads (8 warps, 4(b) x 2(c)), tile 256(b) x 64(c),
// warp tile 64x32 (the R10-proven shape). 2 CTAs/SM co-resident.
// ---------------------------------------------------------------------------
#define KCH    64
#define ROWB   144                    // K-major row stride (128B + 16B pad)
#define A_T    (256 * ROWB)           // 36864 B (A tile, both GEMMs)
#define STG1   (A_T + 64 * ROWB)      // 46080 B (GEMM1: B = 64 K-major rows)
#define STG2   (A_T + 64 * 128)       // 45056 B (GEMM2: B = 64 x 128B swizzled)
#define SMEM_T (2 * STG1)             // 92160 B  -> 184320/SM for 2 CTAs

// ---------------------------------------------------------------------------
// GEMM1 tile: C[256(b) x 64(m)] = state[b][k] * W[m][k], K=4096, 256 tiles.
// Epilogue: e = __expf(beta*acc) -> g_fh + row-sum atomics into g_fsum.
// ---------------------------------------------------------------------------
__device__ __forceinline__ void load_g1(uint32_t sbase, int tid,
                                        const __half* Bp, int ch) {
#pragma unroll
    for (int t2 = 0; t2 < 8; t2++) {           // A: 256 rows x 8 segs (2048)
        int idx = tid + t2 * 256;
        int r = idx >> 3, q = idx & 7;
        cpa16(sbase + (uint32_t)(r * ROWB + q * 16),
              g_sh + (size_t)r * Nc + ch * KCH + q * 8);
    }
#pragma unroll
    for (int t2 = 0; t2 < 2; t2++) {           // B: 64 rows x 8 segs (512)
        int idx = tid + t2 * 256;
        int r = idx >> 3, q = idx & 7;
        cpa16(sbase + A_T + (uint32_t)(r * ROWB + q * 16),
              Bp + (size_t)r * Nc + ch * KCH + q * 8);
    }
}

__device__ void g1_tile(char* smem, int t, float beta) {
    const int tid = threadIdx.x;
    const int wid = tid >> 5;
    const int lid = tid & 31;
    const int rw  = wid & 3;            // warp b-row: 64 rows
    const int cw  = wid >> 2;           // warp m-col: 32 cols (0..1)
    const uint32_t sb = s2u(smem);

    const int c0 = t * 64;
    const __half* Bp = g_Wh + (size_t)c0 * Nc;

    float acc[4][4][4];
#pragma unroll
    for (int i = 0; i < 4; i++)
#pragma unroll
        for (int j = 0; j < 4; j++)
#pragma unroll
            for (int v = 0; v < 4; v++) acc[i][j][v] = 0.0f;

    const int lrow = ((lid >> 3) & 1) * 8 + (lid & 7);
    const int lkb  = (lid >> 4) * 16;

    load_g1(sb, tid, Bp, 0);
    CP_COMMIT();

    for (int ch = 0; ch < 64; ++ch) {
        const uint32_t cur = sb + (uint32_t)(ch & 1) * STG1;
        CP_WAIT(0);
        __syncthreads();
        if (ch + 1 < 64) {
            load_g1(sb + (uint32_t)((ch + 1) & 1) * STG1, tid, Bp, ch + 1);
            CP_COMMIT();
        }

#pragma unroll
        for (int ks = 0; ks < 4; ++ks) {
            uint32_t aF[4][4];
            uint32_t bF[2][4];
#pragma unroll
            for (int sub = 0; sub < 4; ++sub) {
                uint32_t ra = (uint32_t)((rw * 64 + sub * 16 + lrow) * ROWB
                                         + ks * 32 + lkb);
                ldm4(aF[sub], cur + ra);
            }
#pragma unroll
            for (int cg = 0; cg < 2; ++cg) {
                uint32_t rb = (uint32_t)((cw * 32 + cg * 16 + lrow) * ROWB
                                         + ks * 32 + lkb);
                ldm4(bF[cg], cur + A_T + rb);
            }
#pragma unroll
            for (int sub = 0; sub < 4; ++sub)
#pragma unroll
                for (int cg = 0; cg < 2; ++cg)
#pragma unroll
                    for (int hf = 0; hf < 2; ++hf)
                        mma16816(acc[sub][cg * 2 + hf], aF[sub],
                                 bF[cg][hf], bF[cg][hf + 2]);
        }
    }
    __syncthreads();   // stages dead; smem reusable

    // Epilogue: e = __expf(beta*h) -> fp16 g_fh; row sums -> g_fsum
    const int gr = lid >> 2;
    const int gc = (lid & 3) * 2;
    float* rsum = (float*)smem;
    rsum[tid] = 0.0f;
    __syncthreads();

#pragma unroll
    for (int sub = 0; sub < 4; ++sub) {
        const int rbase = rw * 64 + sub * 16 + gr;
        float s0 = 0.0f, s1 = 0.0f;
#pragma unroll
        for (int nt = 0; nt < 4; ++nt) {
            float e0 = __expf(beta * acc[sub][nt][0]);
            float e1 = __expf(beta * acc[sub][nt][1]);
            float e2 = __expf(beta * acc[sub][nt][2]);
            float e3 = __expf(beta * acc[sub][nt][3]);
            const int col = c0 + cw * 32 + nt * 8 + gc;
            *(__half2*)(g_fh + (size_t)rbase * Mc + col) =
                __floats2half2_rn(e0, e1);
            *(__half2*)(g_fh + (size_t)(rbase + 8) * Mc + col) =
                __floats2half2_rn(e2, e3);
            s0 += e0 + e1;
            s1 += e2 + e3;
        }
        s0 += __shfl_xor_sync(0xFFFFFFFF, s0, 1);
        s0 += __shfl_xor_sync(0xFFFFFFFF, s0, 2);
        s1 += __shfl_xor_sync(0xFFFFFFFF, s1, 1);
        s1 += __shfl_xor_sync(0xFFFFFFFF, s1, 2);
        if ((lid & 3) == 0) {
            atomicAdd(&rsum[rbase], s0);
            atomicAdd(&rsum[rbase + 8], s1);
        }
    }
    __syncthreads();
    atomicAdd(&g_fsum[tid], rsum[tid]);
    __syncthreads();
}

// ---------------------------------------------------------------------------
// GEMM2 tile: u[256(b) x 64(n)] = e[b][k] * W[k][n], z-split 4 (K=4096 each),
// 256 tiles. ldmatrix.trans for W (64x128B swizzled rows).
// ---------------------------------------------------------------------------
__device__ __forceinline__ void load_g2(uint32_t sbase, int tid,
                                        const __half* Ap, const __half* Bp, int ch) {
#pragma unroll
    for (int t2 = 0; t2 < 8; t2++) {           // A: 256 rows x 8 segs
        int idx = tid + t2 * 256;
        int r = idx >> 3, q = idx & 7;
        cpa16(sbase + (uint32_t)(r * ROWB + q * 16),
              Ap + (size_t)r * Mc + ch * KCH + q * 8);
    }
#pragma unroll
    for (int t2 = 0; t2 < 2; t2++) {           // B: 64 k-rows x 8 segs, XOR sw
        int idx = tid + t2 * 256;
        int r = idx >> 3, q = idx & 7;
        cpa16(sbase + A_T + (uint32_t)(r * 128 + ((q ^ (r & 7)) * 16)),
              Bp + (size_t)(ch * KCH + r) * Nc + q * 8);
    }
}

__device__ void g2_tile(char* smem, int t) {
    const int tid = threadIdx.x;
    const int wid = tid >> 5;
    const int lid = tid & 31;
    const int rw  = wid & 3;            // warp b-row: 64 rows
    const int cw  = wid >> 2;           // warp n-col: 32 cols (0..1)
    const uint32_t sb = s2u(smem);

    const int z  = t >> 6;
    const int c0 = (t & 63) * 64;
    const size_t koff = (size_t)z * 4096;

    const __half* Ap = g_fh + koff;
    const __half* Bp = g_Wh + koff * Nc + c0;
    float* out = &g_vpart[z][0];

    float acc[4][4][4];
#pragma unroll
    for (int i = 0; i < 4; i++)
#pragma unroll
        for (int j = 0; j < 4; j++)
#pragma unroll
            for (int v = 0; v < 4; v++) acc[i][j][v] = 0.0f;

    const int lrow = ((lid >> 3) & 1) * 8 + (lid & 7);
    const int lkb  = (lid >> 4) * 16;
    const int kr   = ((lid >> 4) & 1) * 8 + (lid & 7);
    const int nso  = (lid >> 3) & 1;

    load_g2(sb, tid, Ap, Bp, 0);
    CP_COMMIT();

    for (int ch = 0; ch < 64; ++ch) {
        const uint32_t cur = sb + (uint32_t)(ch & 1) * STG2;
        CP_WAIT(0);
        __syncthreads();
        if (ch + 1 < 64) {
            load_g2(sb + (uint32_t)((ch + 1) & 1) * STG2, tid, Ap, Bp, ch + 1);
            CP_COMMIT();
        }

#pragma unroll
        for (int ks = 0; ks < 4; ++ks) {
            uint32_t aF[4][4];
            uint32_t bF[2][4];
#pragma unroll
            for (int sub = 0; sub < 4; ++sub) {
                uint32_t ra = (uint32_t)((rw * 64 + sub * 16 + lrow) * ROWB
                                         + ks * 32 + lkb);
                ldm4(aF[sub], cur + ra);
            }
#pragma unroll
            for (int cg = 0; cg < 2; ++cg) {
                const int nseg = cw * 4 + cg * 2 + nso;
                uint32_t rb = (uint32_t)((ks * 16 + kr) * 128
                                         + ((nseg ^ (lid & 7)) * 16));
                ldm4t(bF[cg], cur + A_T + rb);
            }
#pragma unroll
            for (int sub = 0; sub < 4; ++sub)
#pragma unroll
                for (int cg = 0; cg < 2; ++cg)
#pragma unroll
                    for (int hf = 0; hf < 2; ++hf)
                        mma16816(acc[sub][cg * 2 + hf], aF[sub],
                                 bF[cg][hf], bF[cg][hf + 2]);
        }
    }
    __syncthreads();

    const int gr = lid >> 2;
    const int gc = (lid & 3) * 2;
#pragma unroll
    for (int sub = 0; sub < 4; ++sub) {
        const int rbase = rw * 64 + sub * 16 + gr;
#pragma unroll
        for (int nt = 0; nt < 4; ++nt) {
            const int col = c0 + cw * 32 + nt * 8 + gc;
            *(float2*)(out + (size_t)rbase * Nc + col) =
                make_float2(acc[sub][nt][0], acc[sub][nt][1]);
            *(float2*)(out + (size_t)(rbase + 8) * Nc + col) =
                make_float2(acc[sub][nt][2], acc[sub][nt][3]);
        }
    }
    __syncthreads();
}

// ---------------------------------------------------------------------------
// Persistent kernel: all steps + device-side convergence freeze
// ---------------------------------------------------------------------------
__global__ void __launch_bounds__(256, 2) k_steps(float* __restrict__ state,
                                                  const float* __restrict__ beta_p,
                                                  const float* __restrict__ tau_p,
                                                  int G) {
    extern __shared__ char smem[];
    float* red = (float*)smem;
    const int tid = threadIdx.x;
    const float beta = *beta_p;
    const float invtau = 1.0f / (*tau_p);

    for (int step = 0; step < STEPS; ++step) {
        // GEMM1 + fused exp/rowsum (256 tiles)
        for (int t = blockIdx.x; t < 256; t += G) g1_tile(smem, t, beta);
        gbar(G);

        // GEMM2 (256 tiles, z-split 4). CTA 0 snapshots + re-zeros row sums.
        if (blockIdx.x == 0 && tid < Bc) {
            g_fsum2[tid] = g_fsum[tid];
            g_fsum[tid] = 0.0f;
        }
        for (int t = blockIdx.x; t < 256; t += G) g2_tile(smem, t);
        gbar(G);

        // Update + norm (v = (sum of 4 partials) / rowsum)
        float sumsq = 0.0f;
        for (int i = blockIdx.x * 256 + tid; i < Bc * Nc; i += G * 256) {
            int b = i >> 12;                        // Nc = 4096
            float v = (g_vpart[0][i] + g_vpart[1][i] +
                       g_vpart[2][i] + g_vpart[3][i]) / g_fsum2[b];
            float so = state[i];
            float nv = so + invtau * (v - so);
            float d = nv - so;
            sumsq += d * d;
            state[i] = nv;
            g_sh[i] = __float2half(nv);
        }
        red[tid] = sumsq;
        __syncthreads();
        for (int s = 128; s > 0; s >>= 1) {
            if (tid < s) red[tid] += red[tid + s];
            __syncthreads();
        }
        if (tid == 0) atomicAdd(&g_norm[step], red[0]);
        gbar(G);

        float nrm = *(volatile float*)&g_norm[step];
        if (sqrtf(nrm) <= 1e-3f) break;
        __syncthreads();
    }
}

// ---------------------------------------------------------------------------
// kernel_launch
// ---------------------------------------------------------------------------
extern "C" void kernel_launch(void* const* d_in, const int* in_sizes, int n_in,
                              void* d_out, int out_size) {
    const float* inp  = (const float*)d_in[0];
    const float* W    = (const float*)d_in[1];
    const float* beta = (const float*)d_in[2];
    const float* tau  = (const float*)d_in[3];
    float* state = (float*)d_out;

    int dev = 0;
    cudaGetDevice(&dev);
    cudaDeviceProp props;
    cudaGetDeviceProperties(&props, dev);

    cudaFuncSetAttribute(k_steps, cudaFuncAttributeMaxDynamicSharedMemorySize, SMEM_T);

    int occ = 1;
    cudaOccupancyMaxActiveBlocksPerMultiprocessor(&occ, k_steps, 256, SMEM_T);
    if (occ < 1) occ = 1;
    const int G = occ * props.multiProcessorCount;

    k_prep<<<(size_t)Mc * Nc / 1024, 256>>>(W, inp, state);
    k_steps<<<G, 256, SMEM_T>>>(state, beta, tau, G);
}

// round 13
// speedup vs baseline: 1.1243x; 1.1243x over previous
#include <cuda_runtime.h>
#include <cuda_fp16.h>
#include <cstdint>
#include <math.h>

// Problem dims (fixed by the dataset)
#define Bc 256
#define Nc 4096
#define Mc 16384
#define STEPS 50

// ---------------------------------------------------------------------------
// Device-global scratch
// ---------------------------------------------------------------------------
__device__ __half g_Wh[(size_t)Mc * Nc];    // W fp16 [m][n] (both GEMMs)
__device__ __half g_sh[(size_t)Bc * Nc];    // state fp16 [b][n]
__device__ __half g_fh[(size_t)Bc * Mc];    // e = exp(beta*h) fp16 [b][m]
__device__ float  g_fsumP[2][Bc];           // parity row sums
__device__ float  g_vpart[4][(size_t)Bc * Nc];
__device__ float  g_norm[STEPS];
__device__ unsigned g_cntP[2][4];           // parity per-slice g1 completion
__device__ unsigned g_tickP[2];             // parity g2 ticket counters

__device__ unsigned g_cnt_bar;
__device__ volatile unsigned g_gen_bar;

// ---------------------------------------------------------------------------
// PTX helpers (sm_80-era, legal on plain sm_103)
// ---------------------------------------------------------------------------
__device__ __forceinline__ uint32_t s2u(const void* p) {
    return (uint32_t)__cvta_generic_to_shared(p);
}
__device__ __forceinline__ void cpa16(uint32_t dst, const void* src) {
    asm volatile("cp.async.cg.shared.global [%0], [%1], 16;" :: "r"(dst), "l"(src));
}
#define CP_COMMIT() asm volatile("cp.async.commit_group;" ::: "memory")
#define CP_WAIT(n)  asm volatile("cp.async.wait_group %0;" :: "n"(n) : "memory")

__device__ __forceinline__ void ldm4(uint32_t* r, uint32_t addr) {
    asm volatile("ldmatrix.sync.aligned.m8n8.x4.shared.b16 {%0,%1,%2,%3}, [%4];"
                 : "=r"(r[0]), "=r"(r[1]), "=r"(r[2]), "=r"(r[3]) : "r"(addr));
}
__device__ __forceinline__ void ldm4t(uint32_t* r, uint32_t addr) {
    asm volatile("ldmatrix.sync.aligned.m8n8.x4.trans.shared.b16 {%0,%1,%2,%3}, [%4];"
                 : "=r"(r[0]), "=r"(r[1]), "=r"(r[2]), "=r"(r[3]) : "r"(addr));
}
__device__ __forceinline__ void mma16816(float* d, const uint32_t* a,
                                         uint32_t b0, uint32_t b1) {
    asm volatile(
        "mma.sync.aligned.m16n8k16.row.col.f32.f16.f16.f32 "
        "{%0,%1,%2,%3}, {%4,%5,%6,%7}, {%8,%9}, {%0,%1,%2,%3};"
        : "+f"(d[0]), "+f"(d[1]), "+f"(d[2]), "+f"(d[3])
        : "r"(a[0]), "r"(a[1]), "r"(a[2]), "r"(a[3]), "r"(b0), "r"(b1));
}

// ---------------------------------------------------------------------------
// Software global barrier (grid == #SMs, 1 CTA/SM -> co-resident)
// ---------------------------------------------------------------------------
__device__ __forceinline__ void gbar(int G) {
    __syncthreads();
    if (threadIdx.x == 0) {
        __threadfence();
        unsigned my = g_gen_bar;
        unsigned old = atomicAdd(&g_cnt_bar, 1u);
        if (old == (unsigned)G - 1u) {
            g_cnt_bar = 0u;
            __threadfence();
            g_gen_bar = my + 1u;
        } else {
            while (g_gen_bar == my) __nanosleep(64);
        }
        __threadfence();
    }
    __syncthreads();
}

// ---------------------------------------------------------------------------
// Prologue: W -> fp16, state <- input (+fp16), zero all step state
// ---------------------------------------------------------------------------
__global__ void __launch_bounds__(256) k_prep(const float* __restrict__ W,
                                              const float* __restrict__ inp,
                                              float* __restrict__ state) {
    size_t i = (size_t)blockIdx.x * 1024 + threadIdx.x * 4;
    float4 v = *(const float4*)(W + i);
    *(__half2*)(g_Wh + i)     = __floats2half2_rn(v.x, v.y);
    *(__half2*)(g_Wh + i + 2) = __floats2half2_rn(v.z, v.w);

    if (blockIdx.x < (Bc * Nc) / 1024) {
        float4 s = *(const float4*)(inp + i);
        *(float4*)(state + i) = s;
        *(__half2*)(g_sh + i)     = __floats2half2_rn(s.x, s.y);
        *(__half2*)(g_sh + i + 2) = __floats2half2_rn(s.z, s.w);
    }
    int gid = blockIdx.x * 256 + threadIdx.x;
    if (gid < STEPS) g_norm[gid] = 0.0f;
    if (gid < Bc) { g_fsumP[0][gid] = 0.0f; g_fsumP[1][gid] = 0.0f; }
    if (gid < 4)  { g_cntP[0][gid] = 0u;    g_cntP[1][gid] = 0u; }
    if (gid == 4) { g_tickP[0] = 0u;        g_tickP[1] = 0u; }
}

// ---------------------------------------------------------------------------
// Shared sizes (R11-proven)
// ---------------------------------------------------------------------------
#define KCH    64
#define ROWB   144                   // K-major row stride (128B + 16B pad)
#define A1_T   (256 * ROWB)          // 36864 B (A tile, 256 rows)
#define STG1   (A1_T + 128 * ROWB)   // 55296 B (GEMM1 stage)
#define STG2   (A1_T + 64 * 256)     // 53248 B (GEMM2 stage)
#define SMEM_T (2 * STG1)            // 110592 B

// ---------------------------------------------------------------------------
// GEMM1 tile: C[256(b) x 128(m)] = state[b][k] * W[m][k], K=4096, 128 tiles.
// 16 warps 4(b) x 4(m), warp tile 64x32. 2-stage cp.async, 1 sync/chunk.
// Epilogue: e = __expf(beta*acc) -> g_fh + row sums; then slice-signal.
// ---------------------------------------------------------------------------
__device__ __forceinline__ void load_g1(uint32_t sbase, int tid,
                                        const __half* Bp, int ch) {
#pragma unroll
    for (int t2 = 0; t2 < 4; t2++) {           // A: 256 rows x 8 segs
        int idx = tid + t2 * 512;
        int r = idx >> 3, q = idx & 7;
        cpa16(sbase + (uint32_t)(r * ROWB + q * 16),
              g_sh + (size_t)r * Nc + ch * KCH + q * 8);
    }
#pragma unroll
    for (int t2 = 0; t2 < 2; t2++) {           // B: 128 rows x 8 segs
        int idx = tid + t2 * 512;
        int r = idx >> 3, q = idx & 7;
        cpa16(sbase + A1_T + (uint32_t)(r * ROWB + q * 16),
              Bp + (size_t)r * Nc + ch * KCH + q * 8);
    }
}

__device__ void g1_tile(char* smem, int t, float beta,
                        float* fsumA, unsigned* cntA) {
    const int tid = threadIdx.x;
    const int wid = tid >> 5;
    const int lid = tid & 31;
    const int rw  = wid & 3;
    const int cw  = wid >> 2;
    const uint32_t sb = s2u(smem);

    const int c0 = t * 128;
    const __half* Bp = g_Wh + (size_t)c0 * Nc;

    float acc[4][4][4];
#pragma unroll
    for (int i = 0; i < 4; i++)
#pragma unroll
        for (int j = 0; j < 4; j++)
#pragma unroll
            for (int v = 0; v < 4; v++) acc[i][j][v] = 0.0f;

    const int lrow = ((lid >> 3) & 1) * 8 + (lid & 7);
    const int lkb  = (lid >> 4) * 16;

    load_g1(sb, tid, Bp, 0);
    CP_COMMIT();

    for (int ch = 0; ch < 64; ++ch) {
        const uint32_t cur = sb + (uint32_t)(ch & 1) * STG1;
        CP_WAIT(0);
        __syncthreads();
        if (ch + 1 < 64) {
            load_g1(sb + (uint32_t)((ch + 1) & 1) * STG1, tid, Bp, ch + 1);
            CP_COMMIT();
        }

#pragma unroll
        for (int ks = 0; ks < 4; ++ks) {
            uint32_t aF[4][4];
            uint32_t bF[2][4];
#pragma unroll
            for (int sub = 0; sub < 4; ++sub) {
                uint32_t ra = (uint32_t)((rw * 64 + sub * 16 + lrow) * ROWB
                                         + ks * 32 + lkb);
                ldm4(aF[sub], cur + ra);
            }
#pragma unroll
            for (int cg = 0; cg < 2; ++cg) {
                uint32_t rb = (uint32_t)((cw * 32 + cg * 16 + lrow) * ROWB
                                         + ks * 32 + lkb);
                ldm4(bF[cg], cur + A1_T + rb);
            }
#pragma unroll
            for (int sub = 0; sub < 4; ++sub)
#pragma unroll
                for (int cg = 0; cg < 2; ++cg)
#pragma unroll
                    for (int hf = 0; hf < 2; ++hf)
                        mma16816(acc[sub][cg * 2 + hf], aF[sub],
                                 bF[cg][hf], bF[cg][hf + 2]);
        }
    }
    __syncthreads();   // stages dead; smem reusable

    // Epilogue: e = __expf(beta*h) -> fp16 g_fh; row sums -> fsumA
    const int gr = lid >> 2;
    const int gc = (lid & 3) * 2;
    float* rsum = (float*)smem;
    if (tid < 256) rsum[tid] = 0.0f;
    __syncthreads();

#pragma unroll
    for (int sub = 0; sub < 4; ++sub) {
        const int rbase = rw * 64 + sub * 16 + gr;
        float s0 = 0.0f, s1 = 0.0f;
#pragma unroll
        for (int nt = 0; nt < 4; ++nt) {
            float e0 = __expf(beta * acc[sub][nt][0]);
            float e1 = __expf(beta * acc[sub][nt][1]);
            float e2 = __expf(beta * acc[sub][nt][2]);
            float e3 = __expf(beta * acc[sub][nt][3]);
            const int col = c0 + cw * 32 + nt * 8 + gc;
            *(__half2*)(g_fh + (size_t)rbase * Mc + col) =
                __floats2half2_rn(e0, e1);
            *(__half2*)(g_fh + (size_t)(rbase + 8) * Mc + col) =
                __floats2half2_rn(e2, e3);
            s0 += e0 + e1;
            s1 += e2 + e3;
        }
        s0 += __shfl_xor_sync(0xFFFFFFFF, s0, 1);
        s0 += __shfl_xor_sync(0xFFFFFFFF, s0, 2);
        s1 += __shfl_xor_sync(0xFFFFFFFF, s1, 1);
        s1 += __shfl_xor_sync(0xFFFFFFFF, s1, 2);
        if ((lid & 3) == 0) {
            atomicAdd(&rsum[rbase], s0);
            atomicAdd(&rsum[rbase + 8], s1);
        }
    }
    __syncthreads();
    if (tid < 256) atomicAdd(&fsumA[tid], rsum[tid]);
    // release: all this CTA's g_fh stores + fsum atomics, then slice signal
    __threadfence();
    __syncthreads();
    if (tid == 0) atomicAdd(&cntA[t >> 5], 1u);
}

// ---------------------------------------------------------------------------
// GEMM2 tile: u[256(b) x 128(n)] = e[b][k] * W[k][n], z-split 4 (K=4096 each),
// 128 tiles, z = t>>5. ldmatrix.trans for W. (R11-proven)
// ---------------------------------------------------------------------------
__device__ __forceinline__ void load_g2(uint32_t sbase, int tid,
                                        const __half* Ap, const __half* Bp, int ch) {
#pragma unroll
    for (int t2 = 0; t2 < 4; t2++) {           // A: 256 rows x 8 segs (K-major)
        int idx = tid + t2 * 512;
        int r = idx >> 3, q = idx & 7;
        cpa16(sbase + (uint32_t)(r * ROWB + q * 16),
              Ap + (size_t)r * Mc + ch * KCH + q * 8);
    }
#pragma unroll
    for (int t2 = 0; t2 < 2; t2++) {           // B: 64 k-rows x 16 segs, XOR sw
        int idx = tid + t2 * 512;
        int r = idx >> 4, q = idx & 15;
        cpa16(sbase + A1_T + (uint32_t)(r * 256 + ((q ^ (r & 7)) * 16)),
              Bp + (size_t)(ch * KCH + r) * Nc + q * 8);
    }
}

__device__ void g2_tile(char* smem, int t) {
    const int tid = threadIdx.x;
    const int wid = tid >> 5;
    const int lid = tid & 31;
    const int rw  = wid & 3;
    const int cw  = wid >> 2;
    const uint32_t sb = s2u(smem);

    const int z  = t >> 5;
    const int c0 = (t & 31) * 128;
    const size_t koff = (size_t)z * 4096;

    const __half* Ap = g_fh + koff;
    const __half* Bp = g_Wh + koff * Nc + c0;
    float* out = &g_vpart[z][0];

    float acc[4][4][4];
#pragma unroll
    for (int i = 0; i < 4; i++)
#pragma unroll
        for (int j = 0; j < 4; j++)
#pragma unroll
            for (int v = 0; v < 4; v++) acc[i][j][v] = 0.0f;

    const int lrow = ((lid >> 3) & 1) * 8 + (lid & 7);
    const int lkb  = (lid >> 4) * 16;
    const int kr   = ((lid >> 4) & 1) * 8 + (lid & 7);
    const int nso  = (lid >> 3) & 1;

    load_g2(sb, tid, Ap, Bp, 0);
    CP_COMMIT();

    for (int ch = 0; ch < 64; ++ch) {
        const uint32_t cur = sb + (uint32_t)(ch & 1) * STG2;
        CP_WAIT(0);
        __syncthreads();
        if (ch + 1 < 64) {
            load_g2(sb + (uint32_t)((ch + 1) & 1) * STG2, tid, Ap, Bp, ch + 1);
            CP_COMMIT();
        }

#pragma unroll
        for (int ks = 0; ks < 4; ++ks) {
            uint32_t aF[4][4];
            uint32_t bF[2][4];
#pragma unroll
            for (int sub = 0; sub < 4; ++sub) {
                uint32_t ra = (uint32_t)((rw * 64 + sub * 16 + lrow) * ROWB
                                         + ks * 32 + lkb);
                ldm4(aF[sub], cur + ra);
            }
#pragma unroll
            for (int cg = 0; cg < 2; ++cg) {
                const int nseg = cw * 4 + cg * 2 + nso;
                uint32_t rb = (uint32_t)((ks * 16 + kr) * 256
                                         + ((nseg ^ (lid & 7)) * 16));
                ldm4t(bF[cg], cur + A1_T + rb);
            }
#pragma unroll
            for (int sub = 0; sub < 4; ++sub)
#pragma unroll
                for (int cg = 0; cg < 2; ++cg)
#pragma unroll
                    for (int hf = 0; hf < 2; ++hf)
                        mma16816(acc[sub][cg * 2 + hf], aF[sub],
                                 bF[cg][hf], bF[cg][hf + 2]);
        }
    }
    __syncthreads();

    const int gr = lid >> 2;
    const int gc = (lid & 3) * 2;
#pragma unroll
    for (int sub = 0; sub < 4; ++sub) {
        const int rbase = rw * 64 + sub * 16 + gr;
#pragma unroll
        for (int nt = 0; nt < 4; ++nt) {
            const int col = c0 + cw * 32 + nt * 8 + gc;
            *(float2*)(out + (size_t)rbase * Nc + col) =
                make_float2(acc[sub][nt][0], acc[sub][nt][1]);
            *(float2*)(out + (size_t)(rbase + 8) * Nc + col) =
                make_float2(acc[sub][nt][2], acc[sub][nt][3]);
        }
    }
    __syncthreads();
}

// ---------------------------------------------------------------------------
// Persistent kernel: all steps; g1->g2 overlapped via per-slice dataflow
// ---------------------------------------------------------------------------
__global__ void __launch_bounds__(512, 1) k_steps(float* __restrict__ state,
                                                  const float* __restrict__ beta_p,
                                                  const float* __restrict__ tau_p,
                                                  int G) {
    extern __shared__ char smem[];
    float* red = (float*)smem;
    const int tid = threadIdx.x;
    const float beta = *beta_p;
    const float invtau = 1.0f / (*tau_p);

    for (int step = 0; step < STEPS; ++step) {
        const int p = step & 1;
        float*    fsumA = g_fsumP[p];
        unsigned* cntA  = g_cntP[p];

        // GEMM1 + fused exp/rowsum (128 tiles); each tile signals its z-slice
        for (int t = blockIdx.x; t < 128; t += G)
            g1_tile(smem, t, beta, fsumA, cntA);

        // GEMM2 (128 tiles, ticket-dispatched, waits only on its slice)
        for (;;) {
            int* ts = (int*)smem;
            if (tid == 0) ts[0] = (int)atomicAdd(&g_tickP[p], 1u);
            __syncthreads();
            const int t = ts[0];
            __syncthreads();
            if (t >= 128) break;
            if (tid == 0) {
                while (*((volatile unsigned*)&cntA[t >> 5]) < 32u)
                    __nanosleep(32);
            }
            __syncthreads();
            g2_tile(smem, t);
        }
        gbar(G);

        // Update + norm (v = (sum of 4 partials) / rowsum); zero next-parity
        if (blockIdx.x == 0) {
            if (tid < Bc) g_fsumP[p ^ 1][tid] = 0.0f;
            if (tid < 4)  g_cntP[p ^ 1][tid] = 0u;
            if (tid == 4) g_tickP[p ^ 1] = 0u;
        }
        float sumsq = 0.0f;
        for (int i = blockIdx.x * 512 + tid; i < Bc * Nc; i += G * 512) {
            int b = i >> 12;                        // Nc = 4096
            float v = (g_vpart[0][i] + g_vpart[1][i] +
                       g_vpart[2][i] + g_vpart[3][i]) / fsumA[b];
            float so = state[i];
            float nv = so + invtau * (v - so);
            float d = nv - so;
            sumsq += d * d;
            state[i] = nv;
            g_sh[i] = __float2half(nv);
        }
        red[tid] = sumsq;
        __syncthreads();
        for (int s = 256; s > 0; s >>= 1) {
            if (tid < s) red[tid] += red[tid + s];
            __syncthreads();
        }
        if (tid == 0) atomicAdd(&g_norm[step], red[0]);
        gbar(G);

        float nrm = *(volatile float*)&g_norm[step];
        if (sqrtf(nrm) <= 1e-3f) break;
        __syncthreads();
    }
}

// ---------------------------------------------------------------------------
// kernel_launch
// ---------------------------------------------------------------------------
extern "C" void kernel_launch(void* const* d_in, const int* in_sizes, int n_in,
                              void* d_out, int out_size) {
    const float* inp  = (const float*)d_in[0];
    const float* W    = (const float*)d_in[1];
    const float* beta = (const float*)d_in[2];
    const float* tau  = (const float*)d_in[3];
    float* state = (float*)d_out;

    int dev = 0;
    cudaGetDevice(&dev);
    cudaDeviceProp props;
    cudaGetDeviceProperties(&props, dev);
    const int G = props.multiProcessorCount;

    cudaFuncSetAttribute(k_steps, cudaFuncAttributeMaxDynamicSharedMemorySize, SMEM_T);

    k_prep<<<(size_t)Mc * Nc / 1024, 256>>>(W, inp, state);
    k_steps<<<G, 512, SMEM_T>>>(state, beta, tau, G);
}